// round 3
// baseline (speedup 1.0000x reference)
#include <cuda_runtime.h>
#include <math.h>

#define S_LEN 2048
#define BB    4
#define DM    512
#define NH    8
#define DKK   64

typedef unsigned long long u64t;

// ---------------- f32x2 packed-FMA helpers ----------------
__device__ __forceinline__ u64t dup2(float v) {
    u64t r; asm("mov.b64 %0, {%1, %1};" : "=l"(r) : "f"(v)); return r;
}
__device__ __forceinline__ void fma2(u64t &d, u64t a, u64t b) {
    asm("fma.rn.f32x2 %0, %1, %2, %0;" : "+l"(d) : "l"(a), "l"(b));
}
__device__ __forceinline__ void mul2ip(u64t &d, u64t b) {
    asm("mul.rn.f32x2 %0, %0, %1;" : "+l"(d) : "l"(b));
}
__device__ __forceinline__ float2 upk(u64t v) {
    float2 f; asm("mov.b64 {%0, %1}, %2;" : "=f"(f.x), "=f"(f.y) : "l"(v)); return f;
}

// XOR swizzle for transposed A tiles: col' = m ^ SWZ(k). Multiple of 4 so
// 4-row LDS.128 groups stay contiguous.
#define SWZ(k) ((((k) >> 2) & 7) << 2)

// one k-step: 4x4 tile via 8 packed FMAs (A transposed+swizzled, B pair-rows)
#define STEP(AT, BS, kk, ACC)                                                 \
    {                                                                         \
        float4 a4 = *(const float4*)&AT[kk][ty4 ^ SWZ(kk)];                   \
        ulonglong2 b2 = *(const ulonglong2*)&BS[kk][tx4];                     \
        u64t d0 = dup2(a4.x), d1 = dup2(a4.y);                                \
        u64t d2 = dup2(a4.z), d3 = dup2(a4.w);                                \
        fma2(ACC[0][0], d0, b2.x); fma2(ACC[0][1], d0, b2.y);                 \
        fma2(ACC[1][0], d1, b2.x); fma2(ACC[1][1], d1, b2.y);                 \
        fma2(ACC[2][0], d2, b2.x); fma2(ACC[2][1], d2, b2.y);                 \
        fma2(ACC[3][0], d3, b2.x); fma2(ACC[3][1], d3, b2.y);                 \
    }

// ---------------- scratch (device globals; no allocation) ----------------
__device__ float g_w1t[3 * DM * DM];   // conv1 w transposed: [t][ci][co]
__device__ float g_w2t[3 * DM * DM];   // conv2 w transposed
__device__ float g_l1t[DM * DM];       // lin1 w transposed: [k][n]
__device__ float g_l2t[DM * DM];       // lin2 w transposed
__device__ float g_q [BB * NH * S_LEN * DKK];   // [bh][s][d]
__device__ float g_kT[BB * NH * DKK * S_LEN];   // [bh][d][s]  (dim-major)
__device__ float g_v [BB * NH * S_LEN * DKK];   // [bh][s][d]
__device__ float g_o [BB * NH * S_LEN * DKK];   // [bh][s][d]

// ---------------- weight transposes ----------------
__global__ void k_tconv(const float* __restrict__ w, float* __restrict__ wt) {
    int idx = blockIdx.x * 256 + threadIdx.x;       // over DM*DM
    int co = idx & 511, ci = idx >> 9;
    #pragma unroll
    for (int t = 0; t < 3; ++t)
        wt[t * DM * DM + ci * DM + co] = w[(co * DM + ci) * 3 + t];
}

__global__ void k_tlin(const float* __restrict__ w, float* __restrict__ wt) {
    int idx = blockIdx.x * 256 + threadIdx.x;
    int n = idx & 511, k = idx >> 9;
    wt[k * DM + n] = w[n * DM + k];
}

// ---------------- causal conv as GEMM (K = 3*512) ----------------
// x: [S,B,D].  wt: [t][ci][co].  out: head-major; tout=1 -> [bh][d][s]
__global__ void k_conv(const float* __restrict__ x, const float* __restrict__ wt,
                       const float* __restrict__ bias, float* __restrict__ out,
                       int tout)
{
    __shared__ __align__(16) float AsT[64][64];   // transposed+swizzled
    __shared__ __align__(16) float Bs[64][68];
    int tid = threadIdx.x;
    int tx4 = (tid & 15) * 4;
    int ty4 = (tid >> 4) * 4;
    int n0 = blockIdx.x * 64;
    int m0 = blockIdx.y * 64;
    int b  = m0 >> 11;           // m = b*S + s
    int s0 = m0 & 2047;
    int lr = tid >> 4;
    int lc = (tid & 15) * 4;
    int swzA = ((lc >> 2) & 7) << 2;
    u64t acc[4][2] = {};

    for (int chunk = 0; chunk < 24; ++chunk) {
        int t  = chunk >> 3;
        int k0 = (chunk & 7) << 6;
        #pragma unroll
        for (int u = 0; u < 4; ++u) {
            int row = lr + u * 16;
            int ss  = s0 + row + t - 2;
            float4 v = make_float4(0.f, 0.f, 0.f, 0.f);
            if (ss >= 0) v = *(const float4*)&x[(ss * BB + b) * DM + k0 + lc];
            int rc = row ^ swzA;
            AsT[lc + 0][rc] = v.x;
            AsT[lc + 1][rc] = v.y;
            AsT[lc + 2][rc] = v.z;
            AsT[lc + 3][rc] = v.w;
        }
        #pragma unroll
        for (int u = 0; u < 4; ++u) {
            int row = lr + u * 16;
            *(float4*)&Bs[row][lc] =
                *(const float4*)&wt[t * DM * DM + (k0 + row) * DM + n0 + lc];
        }
        __syncthreads();
        #pragma unroll 16
        for (int kk = 0; kk < 64; ++kk) STEP(AsT, Bs, kk, acc)
        __syncthreads();
    }
    int h = n0 >> 6;
    #pragma unroll
    for (int i = 0; i < 4; ++i) {
        int s = s0 + ty4 + i;
        float2 e0 = upk(acc[i][0]);
        float2 e1 = upk(acc[i][1]);
        float4 r = make_float4(e0.x + bias[n0 + tx4 + 0],
                               e0.y + bias[n0 + tx4 + 1],
                               e1.x + bias[n0 + tx4 + 2],
                               e1.y + bias[n0 + tx4 + 3]);
        if (tout) {
            out[((b * NH + h) * DKK + tx4 + 0) * S_LEN + s] = r.x;
            out[((b * NH + h) * DKK + tx4 + 1) * S_LEN + s] = r.y;
            out[((b * NH + h) * DKK + tx4 + 2) * S_LEN + s] = r.z;
            out[((b * NH + h) * DKK + tx4 + 3) * S_LEN + s] = r.w;
        } else {
            *(float4*)&out[((b * NH + h) * S_LEN + s) * DKK + tx4] = r;
        }
    }
}

// ---------------- lin1: v @ W^T + b, out [bh][s][d] ----------------
__global__ void k_lin1(const float* __restrict__ x, const float* __restrict__ wt,
                       const float* __restrict__ bias, float* __restrict__ out)
{
    __shared__ __align__(16) float AsT[64][64];
    __shared__ __align__(16) float Bs[64][68];
    int tid = threadIdx.x;
    int tx4 = (tid & 15) * 4;
    int ty4 = (tid >> 4) * 4;
    int n0 = blockIdx.x * 64;
    int m0 = blockIdx.y * 64;
    int b  = m0 >> 11;
    int s0 = m0 & 2047;
    int lr = tid >> 4;
    int lc = (tid & 15) * 4;
    int swzA = ((lc >> 2) & 7) << 2;
    u64t acc[4][2] = {};

    for (int chunk = 0; chunk < 8; ++chunk) {
        int k0 = chunk << 6;
        #pragma unroll
        for (int u = 0; u < 4; ++u) {
            int row = lr + u * 16;
            float4 v = *(const float4*)&x[((s0 + row) * BB + b) * DM + k0 + lc];
            int rc = row ^ swzA;
            AsT[lc + 0][rc] = v.x;
            AsT[lc + 1][rc] = v.y;
            AsT[lc + 2][rc] = v.z;
            AsT[lc + 3][rc] = v.w;
        }
        #pragma unroll
        for (int u = 0; u < 4; ++u) {
            int row = lr + u * 16;
            *(float4*)&Bs[row][lc] = *(const float4*)&wt[(k0 + row) * DM + n0 + lc];
        }
        __syncthreads();
        #pragma unroll 16
        for (int kk = 0; kk < 64; ++kk) STEP(AsT, Bs, kk, acc)
        __syncthreads();
    }
    int h = n0 >> 6;
    #pragma unroll
    for (int i = 0; i < 4; ++i) {
        int s = s0 + ty4 + i;
        float2 e0 = upk(acc[i][0]);
        float2 e1 = upk(acc[i][1]);
        float4 r = make_float4(e0.x + bias[n0 + tx4 + 0],
                               e0.y + bias[n0 + tx4 + 1],
                               e1.x + bias[n0 + tx4 + 2],
                               e1.y + bias[n0 + tx4 + 3]);
        *(float4*)&out[((b * NH + h) * S_LEN + s) * DKK + tx4] = r;
    }
}

// ---------------- flash attention, causal, dk=64 ----------------
__global__ void k_attn(const float* __restrict__ q, const float* __restrict__ kT,
                       const float* __restrict__ v, float* __restrict__ o)
{
    extern __shared__ __align__(16) float smem[];
    float (*QsT)[64] = (float(*)[64])smem;                     //  4096 f
    float (*Kt)[68]  = (float(*)[68])(smem + 4096);            //  4352 f
    float (*Vs)[68]  = (float(*)[68])(smem + 8448);            //  4352 f
    float (*PsT)[64] = (float(*)[64])(smem + 12800);           //  4096 f

    int tid = threadIdx.x;
    int tx4 = (tid & 15) * 4;
    int ty4 = (tid >> 4) * 4;
    int lr = tid >> 4;
    int lc = (tid & 15) * 4;
    int swzA = ((lc >> 2) & 7) << 2;
    int bh = blockIdx.y;
    int qb = (int)gridDim.x - 1 - (int)blockIdx.x;   // heavy tiles first
    int q0 = qb * 64;

    // load Q tile transposed+swizzled (pre-scaled by 1/sqrt(dk) = 0.125)
    #pragma unroll
    for (int u = 0; u < 4; ++u) {
        int row = lr + u * 16;
        float4 t = *(const float4*)&q[(bh * S_LEN + q0 + row) * DKK + lc];
        int rc = row ^ swzA;
        QsT[lc + 0][rc] = t.x * 0.125f;
        QsT[lc + 1][rc] = t.y * 0.125f;
        QsT[lc + 2][rc] = t.z * 0.125f;
        QsT[lc + 3][rc] = t.w * 0.125f;
    }

    float m_i[4] = {-INFINITY, -INFINITY, -INFINITY, -INFINITY};
    float l_i[4] = {0.f, 0.f, 0.f, 0.f};
    u64t oo[4][2] = {};

    for (int kb = 0; kb <= qb; ++kb) {
        int k0 = kb * 64;
        __syncthreads();   // protect Kt/Vs/PsT from previous iteration's readers
        #pragma unroll
        for (int u = 0; u < 4; ++u) {
            int row = lr + u * 16;
            *(float4*)&Kt[row][lc] =
                *(const float4*)&kT[(bh * DKK + row) * S_LEN + k0 + lc];
            *(float4*)&Vs[row][lc] =
                *(const float4*)&v[(bh * S_LEN + k0 + row) * DKK + lc];
        }
        __syncthreads();

        u64t sc2[4][2] = {};
        #pragma unroll 16
        for (int kk = 0; kk < 64; ++kk) STEP(QsT, Kt, kk, sc2)

        float sc[4][4];
        #pragma unroll
        for (int i = 0; i < 4; ++i) {
            float2 e0 = upk(sc2[i][0]);
            float2 e1 = upk(sc2[i][1]);
            sc[i][0] = e0.x; sc[i][1] = e0.y; sc[i][2] = e1.x; sc[i][3] = e1.y;
        }

        if (kb == qb) {   // diagonal tile: causal mask
            #pragma unroll
            for (int i = 0; i < 4; ++i)
                #pragma unroll
                for (int j = 0; j < 4; ++j)
                    if (tx4 + j > ty4 + i) sc[i][j] = -1e30f;
        }

        // online softmax per row
        #pragma unroll
        for (int i = 0; i < 4; ++i) {
            float tm = fmaxf(fmaxf(sc[i][0], sc[i][1]), fmaxf(sc[i][2], sc[i][3]));
            #pragma unroll
            for (int d = 1; d < 16; d <<= 1)
                tm = fmaxf(tm, __shfl_xor_sync(0xffffffffu, tm, d));
            float mn = fmaxf(m_i[i], tm);
            float corr = __expf(m_i[i] - mn);
            m_i[i] = mn;
            float ps = 0.f;
            #pragma unroll
            for (int j = 0; j < 4; ++j) {
                sc[i][j] = __expf(sc[i][j] - mn);
                ps += sc[i][j];
            }
            #pragma unroll
            for (int d = 1; d < 16; d <<= 1)
                ps += __shfl_xor_sync(0xffffffffu, ps, d);
            l_i[i] = l_i[i] * corr + ps;
            u64t cd = dup2(corr);
            mul2ip(oo[i][0], cd);
            mul2ip(oo[i][1], cd);
        }

        // stage P transposed+swizzled, then O += P @ V
        {
            int swzp = ((tx4 >> 2) & 7) << 2;
            #pragma unroll
            for (int j = 0; j < 4; ++j)
                #pragma unroll
                for (int i = 0; i < 4; ++i)
                    PsT[tx4 + j][(ty4 + i) ^ swzp] = sc[i][j];
        }
        __syncthreads();

        #pragma unroll 16
        for (int c = 0; c < 64; ++c) STEP(PsT, Vs, c, oo)
    }

    #pragma unroll
    for (int i = 0; i < 4; ++i) {
        float inv = 1.f / l_i[i];
        float2 e0 = upk(oo[i][0]);
        float2 e1 = upk(oo[i][1]);
        float4 r = make_float4(e0.x * inv, e0.y * inv, e1.x * inv, e1.y * inv);
        *(float4*)&o[(bh * S_LEN + q0 + ty4 + i) * DKK + tx4] = r;
    }
}

// ---------------- lin2: attn-out @ W^T + b -> [S,B,D] ----------------
__global__ void k_lin2(const float* __restrict__ xo, const float* __restrict__ wt,
                       const float* __restrict__ bias, float* __restrict__ out)
{
    __shared__ __align__(16) float AsT[64][64];
    __shared__ __align__(16) float Bs[64][68];
    int tid = threadIdx.x;
    int tx4 = (tid & 15) * 4;
    int ty4 = (tid >> 4) * 4;
    int n0 = blockIdx.x * 64;
    int m0 = blockIdx.y * 64;
    int b  = m0 >> 11;
    int s0 = m0 & 2047;
    int lr = tid >> 4;
    int lc = (tid & 15) * 4;
    int swzA = ((lc >> 2) & 7) << 2;
    u64t acc[4][2] = {};

    for (int chunk = 0; chunk < 8; ++chunk) {     // chunk == head index h
        int k0 = chunk << 6;
        #pragma unroll
        for (int u = 0; u < 4; ++u) {
            int row = lr + u * 16;
            float4 v = *(const float4*)
                &xo[((b * NH + chunk) * S_LEN + s0 + row) * DKK + lc];
            int rc = row ^ swzA;
            AsT[lc + 0][rc] = v.x;
            AsT[lc + 1][rc] = v.y;
            AsT[lc + 2][rc] = v.z;
            AsT[lc + 3][rc] = v.w;
        }
        #pragma unroll
        for (int u = 0; u < 4; ++u) {
            int row = lr + u * 16;
            *(float4*)&Bs[row][lc] = *(const float4*)&wt[(k0 + row) * DM + n0 + lc];
        }
        __syncthreads();
        #pragma unroll 16
        for (int kk = 0; kk < 64; ++kk) STEP(AsT, Bs, kk, acc)
        __syncthreads();
    }
    #pragma unroll
    for (int i = 0; i < 4; ++i) {
        int s = s0 + ty4 + i;
        float2 e0 = upk(acc[i][0]);
        float2 e1 = upk(acc[i][1]);
        float4 r = make_float4(e0.x + bias[n0 + tx4 + 0],
                               e0.y + bias[n0 + tx4 + 1],
                               e1.x + bias[n0 + tx4 + 2],
                               e1.y + bias[n0 + tx4 + 3]);
        *(float4*)&out[(s * BB + b) * DM + n0 + tx4] = r;
    }
}

// ---------------- launch ----------------
extern "C" void kernel_launch(void* const* d_in, const int* in_sizes, int n_in,
                              void* d_out, int out_size)
{
    (void)in_sizes; (void)n_in; (void)out_size;
    const float* query = (const float*)d_in[0];
    const float* key   = (const float*)d_in[1];
    const float* value = (const float*)d_in[2];
    // d_in[3] = attn_mask: lower-triangular -> handled analytically
    const float* c1w = (const float*)d_in[4];
    const float* c1b = (const float*)d_in[5];
    const float* c2w = (const float*)d_in[6];
    const float* c2b = (const float*)d_in[7];
    const float* l1w = (const float*)d_in[8];
    const float* l1b = (const float*)d_in[9];
    const float* l2w = (const float*)d_in[10];
    const float* l2b = (const float*)d_in[11];
    float* out = (float*)d_out;

    float *w1t, *w2t, *l1t, *l2t, *qb, *kT, *vb, *ob;
    cudaGetSymbolAddress((void**)&w1t, g_w1t);
    cudaGetSymbolAddress((void**)&w2t, g_w2t);
    cudaGetSymbolAddress((void**)&l1t, g_l1t);
    cudaGetSymbolAddress((void**)&l2t, g_l2t);
    cudaGetSymbolAddress((void**)&qb,  g_q);
    cudaGetSymbolAddress((void**)&kT,  g_kT);
    cudaGetSymbolAddress((void**)&vb,  g_v);
    cudaGetSymbolAddress((void**)&ob,  g_o);

    const int ATTN_SMEM = 16896 * 4;  // 67584 B
    cudaFuncSetAttribute(k_attn, cudaFuncAttributeMaxDynamicSharedMemorySize,
                         ATTN_SMEM);

    k_tconv<<<1024, 256>>>(c1w, w1t);
    k_tconv<<<1024, 256>>>(c2w, w2t);
    k_tlin <<<1024, 256>>>(l1w, l1t);
    k_tlin <<<1024, 256>>>(l2w, l2t);

    dim3 gg(DM / 64, (BB * S_LEN) / 64);      // (8, 128)
    k_conv<<<gg, 256>>>(query, w1t, c1b, qb, 0);
    k_conv<<<gg, 256>>>(key,   w2t, c2b, kT, 1);
    k_lin1<<<gg, 256>>>(value, l1t, l1b, vb);

    k_attn<<<dim3(S_LEN / 64, BB * NH), 256, ATTN_SMEM>>>(qb, kT, vb, ob);

    k_lin2<<<gg, 256>>>(ob, l2t, l2b, out);
}

// round 5
// speedup vs baseline: 2.1576x; 2.1576x over previous
#include <cuda_runtime.h>
#include <cuda_bf16.h>
#include <math.h>

#define S_LEN 2048
#define BB    4
#define DM    512
#define NH    8
#define DKK   64
#define SP    36          // u32-pair row stride (conflict-free: bank = 4r+p mod 32)

typedef unsigned int u32;

// ---------------- bf16 split helpers ----------------
__device__ __forceinline__ void bsplit2(float x, float y, u32 &hp, u32 &lp) {
    __nv_bfloat16 xh = __float2bfloat16(x);
    __nv_bfloat16 yh = __float2bfloat16(y);
    float xl = x - __bfloat162float(xh);
    float yl = y - __bfloat162float(yh);
    __nv_bfloat162 hv = __halves2bfloat162(xh, yh);
    __nv_bfloat162 lv = __halves2bfloat162(__float2bfloat16(xl), __float2bfloat16(yl));
    hp = *reinterpret_cast<u32*>(&hv);
    lp = *reinterpret_cast<u32*>(&lv);
}

// mma.m16n8k16 bf16: D += A*B, fp32 accum
__device__ __forceinline__ void mma16(float4 &d, u32 a0, u32 a1, u32 a2, u32 a3,
                                      u32 b0, u32 b1) {
    asm volatile(
        "mma.sync.aligned.m16n8k16.row.col.f32.bf16.bf16.f32 "
        "{%0,%1,%2,%3}, {%4,%5,%6,%7}, {%8,%9}, {%0,%1,%2,%3};"
        : "+f"(d.x), "+f"(d.y), "+f"(d.z), "+f"(d.w)
        : "r"(a0), "r"(a1), "r"(a2), "r"(a3), "r"(b0), "r"(b1));
}

// ---------------- scratch (device globals; no allocation) ----------------
__device__ __nv_bfloat16 g_w1h[3*DM*DM], g_w1l[3*DM*DM];  // conv1 w: [t][co][ci]
__device__ __nv_bfloat16 g_w2h[3*DM*DM], g_w2l[3*DM*DM];  // conv2 w
__device__ __nv_bfloat16 g_l1h[DM*DM],   g_l1l[DM*DM];    // lin1 w: [n][k]
__device__ __nv_bfloat16 g_l2h[DM*DM],   g_l2l[DM*DM];    // lin2 w
__device__ u32 g_qh[BB*NH*S_LEN*32], g_ql[BB*NH*S_LEN*32]; // [bh][s][32 d-pairs]
__device__ u32 g_kh[BB*NH*S_LEN*32], g_kl[BB*NH*S_LEN*32];
__device__ u32 g_oh[BB*NH*S_LEN*32], g_ol[BB*NH*S_LEN*32];
__device__ float g_v[BB*NH*DKK*S_LEN];                     // [bh][d][s] (V^T)

// ---------------- weight prep (split + layout) ----------------
__global__ void k_tconv(const float* __restrict__ w,
                        __nv_bfloat16* __restrict__ wh,
                        __nv_bfloat16* __restrict__ wl) {
    int idx = blockIdx.x * 256 + threadIdx.x;   // over DM*DM
    int co = idx >> 9, ci = idx & 511;
    #pragma unroll
    for (int t = 0; t < 3; ++t) {
        float v = w[(co * DM + ci) * 3 + t];
        __nv_bfloat16 h = __float2bfloat16(v);
        wh[t * DM * DM + co * DM + ci] = h;
        wl[t * DM * DM + co * DM + ci] =
            __float2bfloat16(v - __bfloat162float(h));
    }
}

__global__ void k_tlin(const float* __restrict__ w,
                       __nv_bfloat16* __restrict__ wh,
                       __nv_bfloat16* __restrict__ wl) {
    int idx = blockIdx.x * 256 + threadIdx.x;   // w already [n][k]
    float v = w[idx];
    __nv_bfloat16 h = __float2bfloat16(v);
    wh[idx] = h;
    wl[idx] = __float2bfloat16(v - __bfloat162float(h));
}

// ================= 3-term GEMM chunk (Kc=64) =================
// Ah/Al: [128][SP], Bh/Bl: [64][SP]; warp (wm 0..3, wn 0..1)
#define GEMM_CHUNK3(ACC)                                                      \
    {                                                                         \
        int fr = lane >> 2, fc = lane & 3;                                    \
        _Pragma("unroll")                                                     \
        for (int j = 0; j < 4; ++j) {                                         \
            int kp0 = j * 8 + fc, kp1 = kp0 + 4;                              \
            u32 ah[2][4], al[2][4];                                           \
            _Pragma("unroll")                                                 \
            for (int mi = 0; mi < 2; ++mi) {                                  \
                int br = wm * 32 + mi * 16;                                   \
                ah[mi][0] = Ah[br + fr][kp0]; ah[mi][1] = Ah[br + 8 + fr][kp0];\
                ah[mi][2] = Ah[br + fr][kp1]; ah[mi][3] = Ah[br + 8 + fr][kp1];\
                al[mi][0] = Al[br + fr][kp0]; al[mi][1] = Al[br + 8 + fr][kp0];\
                al[mi][2] = Al[br + fr][kp1]; al[mi][3] = Al[br + 8 + fr][kp1];\
            }                                                                 \
            _Pragma("unroll")                                                 \
            for (int ni = 0; ni < 4; ++ni) {                                  \
                int nn = wn * 32 + ni * 8 + fr;                               \
                u32 bh0 = Bh[nn][kp0], bh1 = Bh[nn][kp1];                     \
                u32 bl0 = Bl[nn][kp0], bl1 = Bl[nn][kp1];                     \
                _Pragma("unroll")                                             \
                for (int mi = 0; mi < 2; ++mi) {                              \
                    mma16(ACC[mi][ni], ah[mi][0], ah[mi][1], ah[mi][2],       \
                          ah[mi][3], bh0, bh1);                               \
                    mma16(ACC[mi][ni], ah[mi][0], ah[mi][1], ah[mi][2],       \
                          ah[mi][3], bl0, bl1);                               \
                    mma16(ACC[mi][ni], al[mi][0], al[mi][1], al[mi][2],       \
                          al[mi][3], bh0, bh1);                               \
                }                                                             \
            }                                                                 \
        }                                                                     \
    }

// stage B tile (64x64 bf16) from [n][k]-layout global hi/lo arrays
#define STAGE_B(WH, WL, GOFF)                                                 \
    {                                                                         \
        int brow = tid >> 2, bq = (tid & 3) * 2;                              \
        const uint4* sh = (const uint4*)&WH[GOFF + brow * DM + k0];           \
        const uint4* sl = (const uint4*)&WL[GOFF + brow * DM + k0];           \
        *(uint4*)&Bh[brow][bq * 4]     = sh[bq];                              \
        *(uint4*)&Bh[brow][bq * 4 + 4] = sh[bq + 1];                          \
        *(uint4*)&Bl[brow][bq * 4]     = sl[bq];                              \
        *(uint4*)&Bl[brow][bq * 4 + 4] = sl[bq + 1];                          \
    }

// ---------------- causal conv as GEMM -> packed Q/K pairs ----------------
__global__ __launch_bounds__(256)
void k_conv(const float* __restrict__ x, const __nv_bfloat16* __restrict__ wh,
            const __nv_bfloat16* __restrict__ wl, const float* __restrict__ bias,
            u32* __restrict__ outh, u32* __restrict__ outl, float scale)
{
    extern __shared__ u32 sm[];
    u32 (*Ah)[SP] = (u32(*)[SP])sm;
    u32 (*Al)[SP] = (u32(*)[SP])(sm + 128 * SP);
    u32 (*Bh)[SP] = (u32(*)[SP])(sm + 256 * SP);
    u32 (*Bl)[SP] = (u32(*)[SP])(sm + 256 * SP + 64 * SP);
    int tid = threadIdx.x, lane = tid & 31, warp = tid >> 5;
    int wm = warp >> 1, wn = warp & 1;
    int n0 = blockIdx.x * 64;
    int m0 = blockIdx.y * 128;
    int b  = m0 >> 11, s0 = m0 & 2047;
    int lr = tid >> 4, lc = (tid & 15) * 4;
    float4 acc[2][4];
    #pragma unroll
    for (int i = 0; i < 2; ++i)
        #pragma unroll
        for (int j = 0; j < 4; ++j) acc[i][j] = make_float4(0.f, 0.f, 0.f, 0.f);

    for (int chunk = 0; chunk < 24; ++chunk) {
        int t  = chunk >> 3;
        int k0 = (chunk & 7) << 6;
        #pragma unroll
        for (int u = 0; u < 8; ++u) {
            int row = lr + u * 16;
            int ss  = s0 + row + t - 2;
            float4 v = make_float4(0.f, 0.f, 0.f, 0.f);
            if (ss >= 0) v = *(const float4*)&x[(ss * BB + b) * DM + k0 + lc];
            u32 h0, l0, h1, l1;
            bsplit2(v.x, v.y, h0, l0);
            bsplit2(v.z, v.w, h1, l1);
            int pc = lc >> 1;
            Ah[row][pc] = h0; Ah[row][pc + 1] = h1;
            Al[row][pc] = l0; Al[row][pc + 1] = l1;
        }
        STAGE_B(wh, wl, t * DM * DM + n0 * DM)
        __syncthreads();
        GEMM_CHUNK3(acc)
        __syncthreads();
    }
    int h = n0 >> 6;
    int fr = lane >> 2, fc = lane & 3;
    #pragma unroll
    for (int mi = 0; mi < 2; ++mi)
        #pragma unroll
        for (int ni = 0; ni < 4; ++ni) {
            int rs = s0 + wm * 32 + mi * 16 + fr;
            int d  = wn * 32 + ni * 8 + fc * 2;
            int pidx = d >> 1;
            float bz0 = bias[n0 + d], bz1 = bias[n0 + d + 1];
            float4 a = acc[mi][ni];
            u32 hp, lp;
            bsplit2((a.x + bz0) * scale, (a.y + bz1) * scale, hp, lp);
            long o0 = ((long)(b * NH + h) * S_LEN + rs) * 32 + pidx;
            outh[o0] = hp; outl[o0] = lp;
            bsplit2((a.z + bz0) * scale, (a.w + bz1) * scale, hp, lp);
            long o1 = o0 + 8 * 32;
            outh[o1] = hp; outl[o1] = lp;
        }
}

// ---------------- lin1: value @ W^T + b -> V^T f32 [bh][d][s] ----------------
__global__ __launch_bounds__(256)
void k_lin1(const float* __restrict__ x, const __nv_bfloat16* __restrict__ wh,
            const __nv_bfloat16* __restrict__ wl, const float* __restrict__ bias,
            float* __restrict__ out)
{
    extern __shared__ u32 sm[];
    u32 (*Ah)[SP] = (u32(*)[SP])sm;
    u32 (*Al)[SP] = (u32(*)[SP])(sm + 128 * SP);
    u32 (*Bh)[SP] = (u32(*)[SP])(sm + 256 * SP);
    u32 (*Bl)[SP] = (u32(*)[SP])(sm + 256 * SP + 64 * SP);
    int tid = threadIdx.x, lane = tid & 31, warp = tid >> 5;
    int wm = warp >> 1, wn = warp & 1;
    int n0 = blockIdx.x * 64;
    int m0 = blockIdx.y * 128;
    int b  = m0 >> 11, s0 = m0 & 2047;
    int lr = tid >> 4, lc = (tid & 15) * 4;
    float4 acc[2][4];
    #pragma unroll
    for (int i = 0; i < 2; ++i)
        #pragma unroll
        for (int j = 0; j < 4; ++j) acc[i][j] = make_float4(0.f, 0.f, 0.f, 0.f);

    for (int chunk = 0; chunk < 8; ++chunk) {
        int k0 = chunk << 6;
        #pragma unroll
        for (int u = 0; u < 8; ++u) {
            int row = lr + u * 16;
            float4 v = *(const float4*)&x[((s0 + row) * BB + b) * DM + k0 + lc];
            u32 h0, l0, h1, l1;
            bsplit2(v.x, v.y, h0, l0);
            bsplit2(v.z, v.w, h1, l1);
            int pc = lc >> 1;
            Ah[row][pc] = h0; Ah[row][pc + 1] = h1;
            Al[row][pc] = l0; Al[row][pc + 1] = l1;
        }
        STAGE_B(wh, wl, n0 * DM)
        __syncthreads();
        GEMM_CHUNK3(acc)
        __syncthreads();
    }
    int h = n0 >> 6;
    int fr = lane >> 2, fc = lane & 3;
    #pragma unroll
    for (int mi = 0; mi < 2; ++mi)
        #pragma unroll
        for (int ni = 0; ni < 4; ++ni) {
            int rs = s0 + wm * 32 + mi * 16 + fr;
            int d  = wn * 32 + ni * 8 + fc * 2;
            float bz0 = bias[n0 + d], bz1 = bias[n0 + d + 1];
            float4 a = acc[mi][ni];
            long base = (long)(b * NH + h) * DKK;
            out[(base + d)     * S_LEN + rs]     = a.x + bz0;
            out[(base + d + 1) * S_LEN + rs]     = a.y + bz1;
            out[(base + d)     * S_LEN + rs + 8] = a.z + bz0;
            out[(base + d + 1) * S_LEN + rs + 8] = a.w + bz1;
        }
}

// ---------------- flash attention (bf16x3 tensor cores) ----------------
__global__ __launch_bounds__(256)
void k_attn(const u32* __restrict__ qh, const u32* __restrict__ ql,
            const u32* __restrict__ kh, const u32* __restrict__ kl,
            const float* __restrict__ vp,
            u32* __restrict__ oh, u32* __restrict__ ol)
{
    extern __shared__ u32 sm[];
    u32 (*Qh)[SP] = (u32(*)[SP])sm;                          // 128*SP
    u32 (*Ql)[SP] = (u32(*)[SP])(sm + 128 * SP);
    u32 (*Kh)[SP] = (u32(*)[SP])(sm + 256 * SP);             // 64*SP
    u32 (*Kl)[SP] = (u32(*)[SP])(sm + 320 * SP);
    u32 (*Vh)[SP] = (u32(*)[SP])(sm + 384 * SP);
    u32 (*Vl)[SP] = (u32(*)[SP])(sm + 448 * SP);
    int tid = threadIdx.x, lane = tid & 31, warp = tid >> 5;
    u32 (*Ph)[SP] = (u32(*)[SP])(sm + 512 * SP + warp * 16 * SP);
    u32 (*Pl)[SP] = (u32(*)[SP])(sm + 640 * SP + warp * 16 * SP);

    int bh = blockIdx.y;
    int qb = (int)gridDim.x - 1 - (int)blockIdx.x;   // heavy tiles first
    int q0 = qb * 128;
    int fr = lane >> 2, fc = lane & 3;
    int wr0 = warp * 16;

    // stage Q (packed copy)
    {
        int row = tid >> 1, h4 = (tid & 1) * 16;
        const uint4* s1 = (const uint4*)&qh[((long)bh * S_LEN + q0 + row) * 32 + h4];
        const uint4* s2 = (const uint4*)&ql[((long)bh * S_LEN + q0 + row) * 32 + h4];
        #pragma unroll
        for (int w = 0; w < 4; ++w) {
            *(uint4*)&Qh[row][h4 + w * 4] = s1[w];
            *(uint4*)&Ql[row][h4 + w * 4] = s2[w];
        }
    }

    float4 Oacc[8];
    #pragma unroll
    for (int i = 0; i < 8; ++i) Oacc[i] = make_float4(0.f, 0.f, 0.f, 0.f);
    float m0r = -INFINITY, m1r = -INFINITY, l0r = 0.f, l1r = 0.f;

    int kmax = 2 * qb + 1;
    for (int kb = 0; kb <= kmax; ++kb) {
        int k0g = kb * 64;
        __syncthreads();
        {   // stage K (packed copy)
            int row = tid >> 2, bq = (tid & 3) * 2;
            const uint4* s1 = (const uint4*)&kh[((long)bh * S_LEN + k0g + row) * 32];
            const uint4* s2 = (const uint4*)&kl[((long)bh * S_LEN + k0g + row) * 32];
            *(uint4*)&Kh[row][bq * 4]     = s1[bq];
            *(uint4*)&Kh[row][bq * 4 + 4] = s1[bq + 1];
            *(uint4*)&Kl[row][bq * 4]     = s2[bq];
            *(uint4*)&Kl[row][bq * 4 + 4] = s2[bq + 1];
        }
        {   // stage V^T (split f32 -> pairs along s)
            int row = tid >> 2, vc = (tid & 3) * 16;
            const float4* sv =
                (const float4*)&vp[((long)bh * DKK + row) * S_LEN + k0g + vc];
            #pragma unroll
            for (int w = 0; w < 4; ++w) {
                float4 f = sv[w];
                u32 h0, l0, h1, l1;
                bsplit2(f.x, f.y, h0, l0);
                bsplit2(f.z, f.w, h1, l1);
                int pc = (vc >> 1) + w * 2;
                Vh[row][pc] = h0; Vh[row][pc + 1] = h1;
                Vl[row][pc] = l0; Vl[row][pc + 1] = l1;
            }
        }
        __syncthreads();

        if (k0g <= q0 + wr0 + 15) {
            float4 S[8];
            #pragma unroll
            for (int i = 0; i < 8; ++i) S[i] = make_float4(0.f, 0.f, 0.f, 0.f);
            #pragma unroll
            for (int j = 0; j < 4; ++j) {
                int kp0 = j * 8 + fc, kp1 = kp0 + 4;
                u32 ah0 = Qh[wr0 + fr][kp0], ah1 = Qh[wr0 + 8 + fr][kp0];
                u32 ah2 = Qh[wr0 + fr][kp1], ah3 = Qh[wr0 + 8 + fr][kp1];
                u32 al0 = Ql[wr0 + fr][kp0], al1 = Ql[wr0 + 8 + fr][kp0];
                u32 al2 = Ql[wr0 + fr][kp1], al3 = Ql[wr0 + 8 + fr][kp1];
                #pragma unroll
                for (int ni = 0; ni < 8; ++ni) {
                    int nn = ni * 8 + fr;
                    u32 bh0 = Kh[nn][kp0], bh1 = Kh[nn][kp1];
                    u32 bl0 = Kl[nn][kp0], bl1 = Kl[nn][kp1];
                    mma16(S[ni], ah0, ah1, ah2, ah3, bh0, bh1);
                    mma16(S[ni], ah0, ah1, ah2, ah3, bl0, bl1);
                    mma16(S[ni], al0, al1, al2, al3, bh0, bh1);
                }
            }
            if (kb >= 2 * qb) {              // diagonal region: causal mask
                int rg0 = q0 + wr0 + fr, rg1 = rg0 + 8;
                #pragma unroll
                for (int ni = 0; ni < 8; ++ni) {
                    int cg = k0g + ni * 8 + fc * 2;
                    if (cg     > rg0) S[ni].x = -1e30f;
                    if (cg + 1 > rg0) S[ni].y = -1e30f;
                    if (cg     > rg1) S[ni].z = -1e30f;
                    if (cg + 1 > rg1) S[ni].w = -1e30f;
                }
            }
            // online softmax (rows fr, fr+8); quad reduce
            float mx0 = -INFINITY, mx1 = -INFINITY;
            #pragma unroll
            for (int ni = 0; ni < 8; ++ni) {
                mx0 = fmaxf(mx0, fmaxf(S[ni].x, S[ni].y));
                mx1 = fmaxf(mx1, fmaxf(S[ni].z, S[ni].w));
            }
            mx0 = fmaxf(mx0, __shfl_xor_sync(0xffffffffu, mx0, 1));
            mx0 = fmaxf(mx0, __shfl_xor_sync(0xffffffffu, mx0, 2));
            mx1 = fmaxf(mx1, __shfl_xor_sync(0xffffffffu, mx1, 1));
            mx1 = fmaxf(mx1, __shfl_xor_sync(0xffffffffu, mx1, 2));
            float mn0 = fmaxf(m0r, mx0), mn1 = fmaxf(m1r, mx1);
            float c0 = __expf(m0r - mn0), c1 = __expf(m1r - mn1);
            m0r = mn0; m1r = mn1;
            float ps0 = 0.f, ps1 = 0.f;
            #pragma unroll
            for (int ni = 0; ni < 8; ++ni) {
                S[ni].x = __expf(S[ni].x - mn0);
                S[ni].y = __expf(S[ni].y - mn0);
                S[ni].z = __expf(S[ni].z - mn1);
                S[ni].w = __expf(S[ni].w - mn1);
                ps0 += S[ni].x + S[ni].y;
                ps1 += S[ni].z + S[ni].w;
            }
            ps0 += __shfl_xor_sync(0xffffffffu, ps0, 1);
            ps0 += __shfl_xor_sync(0xffffffffu, ps0, 2);
            ps1 += __shfl_xor_sync(0xffffffffu, ps1, 1);
            ps1 += __shfl_xor_sync(0xffffffffu, ps1, 2);
            l0r = l0r * c0 + ps0;
            l1r = l1r * c1 + ps1;
            #pragma unroll
            for (int ni = 0; ni < 8; ++ni) {
                Oacc[ni].x *= c0; Oacc[ni].y *= c0;
                Oacc[ni].z *= c1; Oacc[ni].w *= c1;
            }
            // stage P split into per-warp smem
            __syncwarp();
            #pragma unroll
            for (int ni = 0; ni < 8; ++ni) {
                int pidx = ni * 4 + fc;
                u32 hp, lp;
                bsplit2(S[ni].x, S[ni].y, hp, lp);
                Ph[fr][pidx] = hp; Pl[fr][pidx] = lp;
                bsplit2(S[ni].z, S[ni].w, hp, lp);
                Ph[fr + 8][pidx] = hp; Pl[fr + 8][pidx] = lp;
            }
            __syncwarp();
            // O += P @ V
            #pragma unroll
            for (int j = 0; j < 4; ++j) {
                int kp0 = j * 8 + fc, kp1 = kp0 + 4;
                u32 ah0 = Ph[fr][kp0], ah1 = Ph[fr + 8][kp0];
                u32 ah2 = Ph[fr][kp1], ah3 = Ph[fr + 8][kp1];
                u32 al0 = Pl[fr][kp0], al1 = Pl[fr + 8][kp0];
                u32 al2 = Pl[fr][kp1], al3 = Pl[fr + 8][kp1];
                #pragma unroll
                for (int ni = 0; ni < 8; ++ni) {
                    int nn = ni * 8 + fr;
                    u32 bh0 = Vh[nn][kp0], bh1 = Vh[nn][kp1];
                    u32 bl0 = Vl[nn][kp0], bl1 = Vl[nn][kp1];
                    mma16(Oacc[ni], ah0, ah1, ah2, ah3, bh0, bh1);
                    mma16(Oacc[ni], ah0, ah1, ah2, ah3, bl0, bl1);
                    mma16(Oacc[ni], al0, al1, al2, al3, bh0, bh1);
                }
            }
        }
    }

    float inv0 = 1.f / l0r, inv1 = 1.f / l1r;
    #pragma unroll
    for (int ni = 0; ni < 8; ++ni) {
        int pidx = ni * 4 + fc;
        long o0 = ((long)bh * S_LEN + q0 + wr0 + fr) * 32 + pidx;
        u32 hp, lp;
        bsplit2(Oacc[ni].x * inv0, Oacc[ni].y * inv0, hp, lp);
        oh[o0] = hp; ol[o0] = lp;
        bsplit2(Oacc[ni].z * inv1, Oacc[ni].w * inv1, hp, lp);
        oh[o0 + 8 * 32] = hp; ol[o0 + 8 * 32] = lp;
    }
}

// ---------------- lin2: attn-out @ W^T + b -> [S,B,D] f32 ----------------
__global__ __launch_bounds__(256)
void k_lin2(const u32* __restrict__ xh, const u32* __restrict__ xl,
            const __nv_bfloat16* __restrict__ wh, const __nv_bfloat16* __restrict__ wl,
            const float* __restrict__ bias, float* __restrict__ out)
{
    extern __shared__ u32 sm[];
    u32 (*Ah)[SP] = (u32(*)[SP])sm;
    u32 (*Al)[SP] = (u32(*)[SP])(sm + 128 * SP);
    u32 (*Bh)[SP] = (u32(*)[SP])(sm + 256 * SP);
    u32 (*Bl)[SP] = (u32(*)[SP])(sm + 256 * SP + 64 * SP);
    int tid = threadIdx.x, lane = tid & 31, warp = tid >> 5;
    int wm = warp >> 1, wn = warp & 1;
    int n0 = blockIdx.x * 64;
    int m0 = blockIdx.y * 128;
    int b  = m0 >> 11, s0 = m0 & 2047;
    float4 acc[2][4];
    #pragma unroll
    for (int i = 0; i < 2; ++i)
        #pragma unroll
        for (int j = 0; j < 4; ++j) acc[i][j] = make_float4(0.f, 0.f, 0.f, 0.f);

    for (int h = 0; h < 8; ++h) {
        int k0 = h << 6;
        {   // stage A from packed O pairs (pure copy)
            int row = tid >> 1, h4 = (tid & 1) * 16;
            long gb = ((long)(b * NH + h) * S_LEN + s0 + row) * 32 + h4;
            const uint4* s1 = (const uint4*)&xh[gb];
            const uint4* s2 = (const uint4*)&xl[gb];
            #pragma unroll
            for (int w = 0; w < 4; ++w) {
                *(uint4*)&Ah[row][h4 + w * 4] = s1[w];
                *(uint4*)&Al[row][h4 + w * 4] = s2[w];
            }
        }
        STAGE_B(wh, wl, n0 * DM)
        __syncthreads();
        GEMM_CHUNK3(acc)
        __syncthreads();
    }
    int fr = lane >> 2, fc = lane & 3;
    #pragma unroll
    for (int mi = 0; mi < 2; ++mi)
        #pragma unroll
        for (int ni = 0; ni < 4; ++ni) {
            int rs = s0 + wm * 32 + mi * 16 + fr;
            int n  = n0 + wn * 32 + ni * 8 + fc * 2;
            float bz0 = bias[n], bz1 = bias[n + 1];
            float4 a = acc[mi][ni];
            *(float2*)&out[(rs * BB + b) * DM + n] =
                make_float2(a.x + bz0, a.y + bz1);
            *(float2*)&out[((rs + 8) * BB + b) * DM + n] =
                make_float2(a.z + bz0, a.w + bz1);
        }
}

// ---------------- launch ----------------
extern "C" void kernel_launch(void* const* d_in, const int* in_sizes, int n_in,
                              void* d_out, int out_size)
{
    (void)in_sizes; (void)n_in; (void)out_size;
    const float* query = (const float*)d_in[0];
    const float* key   = (const float*)d_in[1];
    const float* value = (const float*)d_in[2];
    // d_in[3] = attn_mask: lower-triangular -> handled analytically
    const float* c1w = (const float*)d_in[4];
    const float* c1b = (const float*)d_in[5];
    const float* c2w = (const float*)d_in[6];
    const float* c2b = (const float*)d_in[7];
    const float* l1w = (const float*)d_in[8];
    const float* l1b = (const float*)d_in[9];
    const float* l2w = (const float*)d_in[10];
    const float* l2b = (const float*)d_in[11];
    float* out = (float*)d_out;

    __nv_bfloat16 *w1h, *w1l, *w2h, *w2l, *l1h, *l1l, *l2h, *l2l;
    u32 *qh, *ql, *kh, *kl, *oh, *ol;
    float *vb;
    cudaGetSymbolAddress((void**)&w1h, g_w1h); cudaGetSymbolAddress((void**)&w1l, g_w1l);
    cudaGetSymbolAddress((void**)&w2h, g_w2h); cudaGetSymbolAddress((void**)&w2l, g_w2l);
    cudaGetSymbolAddress((void**)&l1h, g_l1h); cudaGetSymbolAddress((void**)&l1l, g_l1l);
    cudaGetSymbolAddress((void**)&l2h, g_l2h); cudaGetSymbolAddress((void**)&l2l, g_l2l);
    cudaGetSymbolAddress((void**)&qh, g_qh);   cudaGetSymbolAddress((void**)&ql, g_ql);
    cudaGetSymbolAddress((void**)&kh, g_kh);   cudaGetSymbolAddress((void**)&kl, g_kl);
    cudaGetSymbolAddress((void**)&oh, g_oh);   cudaGetSymbolAddress((void**)&ol, g_ol);
    cudaGetSymbolAddress((void**)&vb, g_v);

    const int GEMM_SMEM = (256 * SP + 128 * SP) * 4;   // 55296 B
    const int ATTN_SMEM = (768 * SP) * 4;              // 110592 B
    cudaFuncSetAttribute(k_conv, cudaFuncAttributeMaxDynamicSharedMemorySize, GEMM_SMEM);
    cudaFuncSetAttribute(k_lin1, cudaFuncAttributeMaxDynamicSharedMemorySize, GEMM_SMEM);
    cudaFuncSetAttribute(k_lin2, cudaFuncAttributeMaxDynamicSharedMemorySize, GEMM_SMEM);
    cudaFuncSetAttribute(k_attn, cudaFuncAttributeMaxDynamicSharedMemorySize, ATTN_SMEM);

    k_tconv<<<1024, 256>>>(c1w, w1h, w1l);
    k_tconv<<<1024, 256>>>(c2w, w2h, w2l);
    k_tlin <<<1024, 256>>>(l1w, l1h, l1l);
    k_tlin <<<1024, 256>>>(l2w, l2h, l2l);

    dim3 gg(DM / 64, (BB * S_LEN) / 128);      // (8, 64)
    k_conv<<<gg, 256, GEMM_SMEM>>>(query, w1h, w1l, c1b, qh, ql, 0.125f);
    k_conv<<<gg, 256, GEMM_SMEM>>>(key,   w2h, w2l, c2b, kh, kl, 1.0f);
    k_lin1<<<gg, 256, GEMM_SMEM>>>(value, l1h, l1l, l1b, vb);

    k_attn<<<dim3(S_LEN / 128, BB * NH), 256, ATTN_SMEM>>>(qh, ql, kh, kl, vb, oh, ol);

    k_lin2<<<gg, 256, GEMM_SMEM>>>(oh, ol, l2h, l2l, l2b, out);
}